// round 12
// baseline (speedup 1.0000x reference)
#include <cuda_runtime.h>

#define N_NODES 100000
#define N_EDGES 3200000
#define CH      16
#define INC     128
#define NB_SCAN 391   // ceil(N_NODES/256)

// Scratch (static __device__ arrays — allocation-free per harness rules)
static __device__ __align__(16) float g_ew[(size_t)N_EDGES * CH];   // [E,16]
static __device__ __align__(16) float g_dinv[N_NODES * CH];
static __device__ __align__(16) float g_h[N_NODES * CH];            // h1lin->hs1->hs2
static __device__ __align__(16) float g_partial[N_NODES * CH];
static __device__ int g_cnt[N_NODES];
static __device__ int g_rowptr[N_NODES + 1];
static __device__ int g_bsum[512];
static __device__ int g_boff[512];
static __device__ int g_cursor[N_NODES];
static __device__ int g_elist[N_EDGES];

__device__ __forceinline__ void red_add_v4(float4* addr, float4 v) {
    asm volatile("red.global.add.v4.f32 [%0], {%1, %2, %3, %4};"
                 :: "l"(addr), "f"(v.x), "f"(v.y), "f"(v.z), "f"(v.w)
                 : "memory");
}

// ---------- CSR build ----------
__global__ void k_zero_cnt(void) {
    int i = blockIdx.x * blockDim.x + threadIdx.x;
    if (i < N_NODES) g_cnt[i] = 0;
}

__global__ void k_hist(const int* __restrict__ dstp) {
    int e = blockIdx.x * blockDim.x + threadIdx.x;
    if (e < N_EDGES) atomicAdd(&g_cnt[dstp[e]], 1);
}

__global__ void k_scan_block(void) {
    __shared__ int s[256];
    int i = blockIdx.x * 256 + threadIdx.x;
    int v = (i < N_NODES) ? g_cnt[i] : 0;
    s[threadIdx.x] = v;
    __syncthreads();
#pragma unroll
    for (int off = 1; off < 256; off <<= 1) {
        int t = (threadIdx.x >= off) ? s[threadIdx.x - off] : 0;
        __syncthreads();
        s[threadIdx.x] += t;
        __syncthreads();
    }
    if (i < N_NODES) g_rowptr[i] = s[threadIdx.x] - v;  // exclusive within block
    if (threadIdx.x == 255) g_bsum[blockIdx.x] = s[255];
}

__global__ void k_scan_tot(void) {
    __shared__ int s[512];
    int tid = threadIdx.x;
    int v = (tid < NB_SCAN) ? g_bsum[tid] : 0;
    s[tid] = v;
    __syncthreads();
#pragma unroll
    for (int off = 1; off < 512; off <<= 1) {
        int t = (tid >= off) ? s[tid - off] : 0;
        __syncthreads();
        s[tid] += t;
        __syncthreads();
    }
    g_boff[tid] = s[tid] - v;  // exclusive
}

__global__ void k_scan_add(void) {
    int i = blockIdx.x * blockDim.x + threadIdx.x;
    if (i < N_NODES) {
        g_rowptr[i] += g_boff[i >> 8];
        g_cursor[i] = 0;
    }
    if (i == 0) g_rowptr[N_NODES] = N_EDGES;
}

__global__ void k_fill(const int* __restrict__ dstp) {
    int e = blockIdx.x * blockDim.x + threadIdx.x;
    if (e >= N_EDGES) return;
    int d = dstp[e];
    int pos = g_rowptr[d] + atomicAdd(&g_cursor[d], 1);
    g_elist[pos] = e;
}

// Per-node ascending sort of edge ids (sequential update order of CPU scatter)
__global__ void k_sort(void) {
    int n = blockIdx.x * blockDim.x + threadIdx.x;
    if (n >= N_NODES) return;
    int lo = g_rowptr[n], hi = g_rowptr[n + 1];
    for (int i = lo + 1; i < hi; i++) {
        int v = g_elist[i];
        int j = i - 1;
        while (j >= lo && g_elist[j] > v) { g_elist[j + 1] = g_elist[j]; j--; }
        g_elist[j + 1] = v;
    }
}

// ---------- ew = edge_attr @ We + be ----------
// aarch64 NEON-style k-vectorized dot: 4 FUSED lane accumulators (fmla),
// lane = k mod 4, ascending k-groups, pairwise combine (l0+l1)+(l2+l3), bias last.
__global__ void __launch_bounds__(256) k_ew(
        const float* __restrict__ ea, const float* __restrict__ We,
        const float* __restrict__ be) {
    __shared__ float Ws[CH * CH];
    __shared__ float bs[CH];
    if (threadIdx.x < CH * CH) Ws[threadIdx.x] = We[threadIdx.x];
    if (threadIdx.x < CH) bs[threadIdx.x] = be[threadIdx.x];
    __syncthreads();
    int e = blockIdx.x * blockDim.x + threadIdx.x;
    if (e >= N_EDGES) return;
    const float4* ear = reinterpret_cast<const float4*>(ea) + (size_t)e * 4;
    float4 a0 = __ldcs(ear + 0), a1 = __ldcs(ear + 1);
    float4 a2 = __ldcs(ear + 2), a3 = __ldcs(ear + 3);
    float av[CH] = {a0.x, a0.y, a0.z, a0.w, a1.x, a1.y, a1.z, a1.w,
                    a2.x, a2.y, a2.z, a2.w, a3.x, a3.y, a3.z, a3.w};
    float w[CH];
#pragma unroll
    for (int j = 0; j < CH; j++) {
        float acc0 = 0.f, acc1 = 0.f, acc2 = 0.f, acc3 = 0.f;
#pragma unroll
        for (int g = 0; g < 4; g++) {
            acc0 = fmaf(av[4 * g + 0], Ws[(4 * g + 0) * CH + j], acc0);  // fused lanes
            acc1 = fmaf(av[4 * g + 1], Ws[(4 * g + 1) * CH + j], acc1);
            acc2 = fmaf(av[4 * g + 2], Ws[(4 * g + 2) * CH + j], acc2);
            acc3 = fmaf(av[4 * g + 3], Ws[(4 * g + 3) * CH + j], acc3);
        }
        float s01 = __fadd_rn(acc0, acc1);
        float s23 = __fadd_rn(acc2, acc3);
        w[j] = __fadd_rn(__fadd_rn(s01, s23), bs[j]);
    }
    float4* ewp = reinterpret_cast<float4*>(&g_ew[(size_t)e * CH]);
    __stcs(ewp + 0, make_float4(w[0],  w[1],  w[2],  w[3]));
    __stcs(ewp + 1, make_float4(w[4],  w[5],  w[6],  w[7]));
    __stcs(ewp + 2, make_float4(w[8],  w[9],  w[10], w[11]));
    __stcs(ewp + 3, make_float4(w[12], w[13], w[14], w[15]));
}

// ---------- h1lin = x @ W1 (fp32; non-amplified) ----------
__global__ void __launch_bounds__(256) k_xw(
        const float* __restrict__ x, const float* __restrict__ W1) {
    __shared__ float W1s[INC * CH];
    for (int i = threadIdx.x; i < INC * CH; i += blockDim.x) W1s[i] = W1[i];
    __syncthreads();
    int n = blockIdx.x * blockDim.x + threadIdx.x;
    if (n >= N_NODES) return;
    float acc[CH];
#pragma unroll
    for (int j = 0; j < CH; j++) acc[j] = 0.f;
    const float4* xr = reinterpret_cast<const float4*>(x) + (size_t)n * (INC / 4);
#pragma unroll 4
    for (int k4 = 0; k4 < INC / 4; k4++) {
        float4 xv = __ldg(xr + k4);
        const float* w0 = &W1s[(k4 * 4 + 0) * CH];
        const float* w1 = &W1s[(k4 * 4 + 1) * CH];
        const float* w2 = &W1s[(k4 * 4 + 2) * CH];
        const float* w3 = &W1s[(k4 * 4 + 3) * CH];
#pragma unroll
        for (int j = 0; j < CH; j++) {
            acc[j] = fmaf(xv.x, w0[j], acc[j]);
            acc[j] = fmaf(xv.y, w1[j], acc[j]);
            acc[j] = fmaf(xv.z, w2[j], acc[j]);
            acc[j] = fmaf(xv.w, w3[j], acc[j]);
        }
    }
    float4* hp = reinterpret_cast<float4*>(&g_h[n * CH]);
#pragma unroll
    for (int i = 0; i < 4; i++)
        hp[i] = make_float4(acc[4 * i], acc[4 * i + 1], acc[4 * i + 2], acc[4 * i + 3]);
}

// ---------- deg: sequential ascending-e fp32 sum, +1.0 last; dinv; hs1; partial=0 ----------
__global__ void __launch_bounds__(128) k_deg_dinv_hs1(void) {
    int t = blockIdx.x * blockDim.x + threadIdx.x;
    int n = t >> 4;
    int c = t & 15;
    if (n >= N_NODES) return;
    int lo = g_rowptr[n], hi = g_rowptr[n + 1];
    float acc = 0.f;
    for (int i = lo; i < hi; i++) {
        int e = g_elist[i];
        acc = __fadd_rn(acc, __ldg(&g_ew[(size_t)e * CH + c]));
    }
    float deg = __fadd_rn(acc, 1.0f);
    float dinv = 0.f;
    if (deg > 0.f) {
        double dd = (double)fabsf(deg) + 1e-12;
        dinv = (float)(1.0 / sqrt(dd));
    }
    int idx = n * CH + c;
    g_dinv[idx] = dinv;
    g_h[idx] = dinv * g_h[idx];  // hs1
    g_partial[idx] = 0.f;
}

// ---------- edge scatter: partial[dst] += ew * hs[src] ----------
__global__ void __launch_bounds__(256) k_edge_scatter(
        const int* __restrict__ srcp, const int* __restrict__ dstp) {
    int e = blockIdx.x * blockDim.x + threadIdx.x;
    if (e >= N_EDGES) return;
    int s = __ldg(srcp + e);
    int d = __ldg(dstp + e);
    const float4* ewp = reinterpret_cast<const float4*>(&g_ew[(size_t)e * CH]);
    const float4* hp  = reinterpret_cast<const float4*>(&g_h[s * CH]);
    float4* pp = reinterpret_cast<float4*>(&g_partial[d * CH]);
#pragma unroll
    for (int i = 0; i < 4; i++) {
        float4 w = __ldcs(ewp + i);
        float4 h = __ldg(hp + i);
        red_add_v4(pp + i, make_float4(w.x * h.x, w.y * h.y, w.z * h.z, w.w * h.w));
    }
}

// ---------- layer-1 finish: h = relu(dinv*(partial+hs1)+b1); hs2 = dinv*(h@W2); partial=0 ----------
__global__ void __launch_bounds__(256) k_layer1_finish(
        const float* __restrict__ b1, const float* __restrict__ W2) {
    __shared__ float W2s[CH * CH];
    __shared__ float b1s[CH];
    if (threadIdx.x < CH * CH) W2s[threadIdx.x] = W2[threadIdx.x];
    if (threadIdx.x < CH) b1s[threadIdx.x] = b1[threadIdx.x];
    __syncthreads();
    int n = blockIdx.x * blockDim.x + threadIdx.x;
    if (n >= N_NODES) return;
    float h[CH], dv[CH];
    const float4* d4p = reinterpret_cast<const float4*>(&g_dinv[n * CH]);
    const float4* p4p = reinterpret_cast<const float4*>(&g_partial[n * CH]);
    float4* h4p = reinterpret_cast<float4*>(&g_h[n * CH]);
#pragma unroll
    for (int i = 0; i < 4; i++) {
        float4 d4 = d4p[i];
        float4 p4 = p4p[i];
        float4 s4 = h4p[i];  // hs1
        dv[4 * i + 0] = d4.x; dv[4 * i + 1] = d4.y; dv[4 * i + 2] = d4.z; dv[4 * i + 3] = d4.w;
        h[4 * i + 0] = fmaxf(d4.x * (p4.x + s4.x) + b1s[4 * i + 0], 0.f);
        h[4 * i + 1] = fmaxf(d4.y * (p4.y + s4.y) + b1s[4 * i + 1], 0.f);
        h[4 * i + 2] = fmaxf(d4.z * (p4.z + s4.z) + b1s[4 * i + 2], 0.f);
        h[4 * i + 3] = fmaxf(d4.w * (p4.w + s4.w) + b1s[4 * i + 3], 0.f);
    }
    float acc[CH];
#pragma unroll
    for (int j = 0; j < CH; j++) acc[j] = 0.f;
#pragma unroll
    for (int k = 0; k < CH; k++) {
        float hk = h[k];
#pragma unroll
        for (int j = 0; j < CH; j++) acc[j] = fmaf(hk, W2s[k * CH + j], acc[j]);
    }
    float4* pz = reinterpret_cast<float4*>(&g_partial[n * CH]);
    float4 zero = make_float4(0.f, 0.f, 0.f, 0.f);
#pragma unroll
    for (int i = 0; i < 4; i++) {
        h4p[i] = make_float4(dv[4 * i + 0] * acc[4 * i + 0],
                             dv[4 * i + 1] * acc[4 * i + 1],
                             dv[4 * i + 2] * acc[4 * i + 2],
                             dv[4 * i + 3] * acc[4 * i + 3]);  // hs2
        pz[i] = zero;
    }
}

// ---------- out = dinv*(partial + hs2) + b2 ----------
__global__ void __launch_bounds__(256) k_out(
        const float* __restrict__ b2, float* __restrict__ out) {
    int n = blockIdx.x * blockDim.x + threadIdx.x;
    if (n >= N_NODES) return;
    float4* o4 = reinterpret_cast<float4*>(out);
    const float4* d4p = reinterpret_cast<const float4*>(&g_dinv[n * CH]);
    const float4* p4p = reinterpret_cast<const float4*>(&g_partial[n * CH]);
    const float4* s4p = reinterpret_cast<const float4*>(&g_h[n * CH]);
#pragma unroll
    for (int i = 0; i < 4; i++) {
        float4 d4 = d4p[i];
        float4 p4 = p4p[i];
        float4 s4 = s4p[i];
        float4 o;
        o.x = d4.x * (p4.x + s4.x) + __ldg(b2 + 4 * i + 0);
        o.y = d4.y * (p4.y + s4.y) + __ldg(b2 + 4 * i + 1);
        o.z = d4.z * (p4.z + s4.z) + __ldg(b2 + 4 * i + 2);
        o.w = d4.w * (p4.w + s4.w) + __ldg(b2 + 4 * i + 3);
        o4[n * 4 + i] = o;
    }
}

extern "C" void kernel_launch(void* const* d_in, const int* in_sizes, int n_in,
                              void* d_out, int out_size) {
    const float* x  = (const float*)d_in[0];
    const int*   ei = (const int*)d_in[1];
    const float* ea = (const float*)d_in[2];
    const float* We = (const float*)d_in[3];
    const float* be = (const float*)d_in[4];
    const float* W1 = (const float*)d_in[5];
    const float* b1 = (const float*)d_in[6];
    const float* W2 = (const float*)d_in[7];
    const float* b2 = (const float*)d_in[8];
    const int* srcp = ei;
    const int* dstp = ei + N_EDGES;
    float* out = (float*)d_out;

    const int nb_n  = (N_NODES + 255) / 256;
    const int nb_e  = (N_EDGES + 255) / 256;
    const int nb_nc = (N_NODES * CH + 127) / 128;

    // CSR build (stable sorted-by-dst order, ascending-e within node)
    k_zero_cnt   <<<nb_n, 256>>>();
    k_hist       <<<nb_e, 256>>>(dstp);
    k_scan_block <<<NB_SCAN, 256>>>();
    k_scan_tot   <<<1, 512>>>();
    k_scan_add   <<<nb_n, 256>>>();
    k_fill       <<<nb_e, 256>>>(dstp);
    k_sort       <<<nb_n, 256>>>();

    // Main pipeline
    k_ew            <<<nb_e, 256>>>(ea, We, be);   // 4-lane FUSED NEON-style ew
    k_xw            <<<nb_n, 256>>>(x, W1);
    k_deg_dinv_hs1  <<<nb_nc, 128>>>();            // sequential ascending deg
    k_edge_scatter  <<<nb_e, 256>>>(srcp, dstp);
    k_layer1_finish <<<nb_n, 256>>>(b1, W2);
    k_edge_scatter  <<<nb_e, 256>>>(srcp, dstp);
    k_out           <<<nb_n, 256>>>(b2, out);
}

// round 13
// speedup vs baseline: 1.0001x; 1.0001x over previous
#include <cuda_runtime.h>

#define N_NODES 100000
#define N_EDGES 3200000
#define CH      16
#define INC     128
#define NB_SCAN 391   // ceil(N_NODES/256)

// Scratch (static __device__ arrays — allocation-free per harness rules)
static __device__ __align__(16) float g_ew[(size_t)N_EDGES * CH];   // [E,16]
static __device__ __align__(16) float g_dinv[N_NODES * CH];
static __device__ __align__(16) float g_h[N_NODES * CH];            // h1lin->hs1->hs2
static __device__ __align__(16) float g_partial[N_NODES * CH];
static __device__ int g_cnt[N_NODES];
static __device__ int g_rowptr[N_NODES + 1];
static __device__ int g_bsum[512];
static __device__ int g_boff[512];
static __device__ int g_cursor[N_NODES];
static __device__ int g_elist[N_EDGES];

__device__ __forceinline__ void red_add_v4(float4* addr, float4 v) {
    asm volatile("red.global.add.v4.f32 [%0], {%1, %2, %3, %4};"
                 :: "l"(addr), "f"(v.x), "f"(v.y), "f"(v.z), "f"(v.w)
                 : "memory");
}

// ---------- CSR build ----------
__global__ void k_zero_cnt(void) {
    int i = blockIdx.x * blockDim.x + threadIdx.x;
    if (i < N_NODES) g_cnt[i] = 0;
}

// ---------- ew = edge_attr @ We + be  (+ fused dst histogram) ----------
// BIT-CONTRACT (matches reference, do not change): aarch64 NEON-style
// k-vectorized dot, 4 FUSED lane accumulators (lane = k mod 4) over ascending
// k-groups, pairwise combine (l0+l1)+(l2+l3), bias last.
__global__ void __launch_bounds__(256) k_ew_hist(
        const float* __restrict__ ea, const float* __restrict__ We,
        const float* __restrict__ be, const int* __restrict__ dstp) {
    __shared__ float Ws[CH * CH];
    __shared__ float bs[CH];
    if (threadIdx.x < CH * CH) Ws[threadIdx.x] = We[threadIdx.x];
    if (threadIdx.x < CH) bs[threadIdx.x] = be[threadIdx.x];
    __syncthreads();
    int e = blockIdx.x * blockDim.x + threadIdx.x;
    if (e >= N_EDGES) return;
    const float4* ear = reinterpret_cast<const float4*>(ea) + (size_t)e * 4;
    float4 a0 = __ldcs(ear + 0), a1 = __ldcs(ear + 1);
    float4 a2 = __ldcs(ear + 2), a3 = __ldcs(ear + 3);
    float av[CH] = {a0.x, a0.y, a0.z, a0.w, a1.x, a1.y, a1.z, a1.w,
                    a2.x, a2.y, a2.z, a2.w, a3.x, a3.y, a3.z, a3.w};
    float w[CH];
#pragma unroll
    for (int j = 0; j < CH; j++) {
        float acc0 = 0.f, acc1 = 0.f, acc2 = 0.f, acc3 = 0.f;
#pragma unroll
        for (int g = 0; g < 4; g++) {
            acc0 = fmaf(av[4 * g + 0], Ws[(4 * g + 0) * CH + j], acc0);
            acc1 = fmaf(av[4 * g + 1], Ws[(4 * g + 1) * CH + j], acc1);
            acc2 = fmaf(av[4 * g + 2], Ws[(4 * g + 2) * CH + j], acc2);
            acc3 = fmaf(av[4 * g + 3], Ws[(4 * g + 3) * CH + j], acc3);
        }
        float s01 = __fadd_rn(acc0, acc1);
        float s23 = __fadd_rn(acc2, acc3);
        w[j] = __fadd_rn(__fadd_rn(s01, s23), bs[j]);
    }
    float4* ewp = reinterpret_cast<float4*>(&g_ew[(size_t)e * CH]);
    __stcs(ewp + 0, make_float4(w[0],  w[1],  w[2],  w[3]));
    __stcs(ewp + 1, make_float4(w[4],  w[5],  w[6],  w[7]));
    __stcs(ewp + 2, make_float4(w[8],  w[9],  w[10], w[11]));
    __stcs(ewp + 3, make_float4(w[12], w[13], w[14], w[15]));
    atomicAdd(&g_cnt[__ldg(dstp + e)], 1);   // fused histogram
}

__global__ void k_scan_block(void) {
    __shared__ int s[256];
    int i = blockIdx.x * 256 + threadIdx.x;
    int v = (i < N_NODES) ? g_cnt[i] : 0;
    s[threadIdx.x] = v;
    __syncthreads();
#pragma unroll
    for (int off = 1; off < 256; off <<= 1) {
        int t = (threadIdx.x >= off) ? s[threadIdx.x - off] : 0;
        __syncthreads();
        s[threadIdx.x] += t;
        __syncthreads();
    }
    if (i < N_NODES) g_rowptr[i] = s[threadIdx.x] - v;  // exclusive within block
    if (threadIdx.x == 255) g_bsum[blockIdx.x] = s[255];
}

__global__ void k_scan_tot(void) {
    __shared__ int s[512];
    int tid = threadIdx.x;
    int v = (tid < NB_SCAN) ? g_bsum[tid] : 0;
    s[tid] = v;
    __syncthreads();
#pragma unroll
    for (int off = 1; off < 512; off <<= 1) {
        int t = (tid >= off) ? s[tid - off] : 0;
        __syncthreads();
        s[tid] += t;
        __syncthreads();
    }
    g_boff[tid] = s[tid] - v;  // exclusive
}

__global__ void k_scan_add(void) {
    int i = blockIdx.x * blockDim.x + threadIdx.x;
    if (i < N_NODES) {
        g_rowptr[i] += g_boff[i >> 8];
        g_cursor[i] = 0;
    }
    if (i == 0) g_rowptr[N_NODES] = N_EDGES;
}

__global__ void k_fill(const int* __restrict__ dstp) {
    int e = blockIdx.x * blockDim.x + threadIdx.x;
    if (e >= N_EDGES) return;
    int d = dstp[e];
    int pos = g_rowptr[d] + atomicAdd(&g_cursor[d], 1);
    g_elist[pos] = e;
}

// Per-node ascending sort of edge ids — staged in shared memory.
// 64 threads/block, one node per thread, 97-padded rows (conflict-free).
__global__ void __launch_bounds__(64) k_sort(void) {
    __shared__ int buf[64][97];
    int n = blockIdx.x * 64 + threadIdx.x;
    if (n >= N_NODES) return;
    int lo = g_rowptr[n], hi = g_rowptr[n + 1];
    int L = hi - lo;
    if (L <= 96) {
        int* b = buf[threadIdx.x];
        for (int i = 0; i < L; i++) b[i] = g_elist[lo + i];
        for (int i = 1; i < L; i++) {
            int v = b[i];
            int j = i - 1;
            while (j >= 0 && b[j] > v) { b[j + 1] = b[j]; j--; }
            b[j + 1] = v;
        }
        for (int i = 0; i < L; i++) g_elist[lo + i] = b[i];
    } else {
        // statistically unreachable fallback (Poisson(32) max << 96)
        for (int i = lo + 1; i < hi; i++) {
            int v = g_elist[i];
            int j = i - 1;
            while (j >= lo && g_elist[j] > v) { g_elist[j + 1] = g_elist[j]; j--; }
            g_elist[j + 1] = v;
        }
    }
}

// ---------- h1lin = x @ W1 (fp32; non-amplified) ----------
__global__ void __launch_bounds__(256) k_xw(
        const float* __restrict__ x, const float* __restrict__ W1) {
    __shared__ float W1s[INC * CH];
    for (int i = threadIdx.x; i < INC * CH; i += blockDim.x) W1s[i] = W1[i];
    __syncthreads();
    int n = blockIdx.x * blockDim.x + threadIdx.x;
    if (n >= N_NODES) return;
    float acc[CH];
#pragma unroll
    for (int j = 0; j < CH; j++) acc[j] = 0.f;
    const float4* xr = reinterpret_cast<const float4*>(x) + (size_t)n * (INC / 4);
#pragma unroll 4
    for (int k4 = 0; k4 < INC / 4; k4++) {
        float4 xv = __ldg(xr + k4);
        const float* w0 = &W1s[(k4 * 4 + 0) * CH];
        const float* w1 = &W1s[(k4 * 4 + 1) * CH];
        const float* w2 = &W1s[(k4 * 4 + 2) * CH];
        const float* w3 = &W1s[(k4 * 4 + 3) * CH];
#pragma unroll
        for (int j = 0; j < CH; j++) {
            acc[j] = fmaf(xv.x, w0[j], acc[j]);
            acc[j] = fmaf(xv.y, w1[j], acc[j]);
            acc[j] = fmaf(xv.z, w2[j], acc[j]);
            acc[j] = fmaf(xv.w, w3[j], acc[j]);
        }
    }
    float4* hp = reinterpret_cast<float4*>(&g_h[n * CH]);
#pragma unroll
    for (int i = 0; i < 4; i++)
        hp[i] = make_float4(acc[4 * i], acc[4 * i + 1], acc[4 * i + 2], acc[4 * i + 3]);
}

// ---------- deg: BIT-CONTRACT sequential ascending-e fp32 sum, +1.0 last ----------
__global__ void __launch_bounds__(128) k_deg_dinv_hs1(void) {
    int t = blockIdx.x * blockDim.x + threadIdx.x;
    int n = t >> 4;
    int c = t & 15;
    if (n >= N_NODES) return;
    int lo = g_rowptr[n], hi = g_rowptr[n + 1];
    float acc = 0.f;
    for (int i = lo; i < hi; i++) {
        int e = g_elist[i];
        acc = __fadd_rn(acc, __ldg(&g_ew[(size_t)e * CH + c]));
    }
    float deg = __fadd_rn(acc, 1.0f);
    float dinv = 0.f;
    if (deg > 0.f) {
        double dd = (double)fabsf(deg) + 1e-12;
        dinv = (float)(1.0 / sqrt(dd));
    }
    int idx = n * CH + c;
    g_dinv[idx] = dinv;
    g_h[idx] = dinv * g_h[idx];  // hs1
    g_partial[idx] = 0.f;
}

// ---------- edge scatter: partial[dst] += ew * hs[src] ----------
__global__ void __launch_bounds__(256) k_edge_scatter(
        const int* __restrict__ srcp, const int* __restrict__ dstp) {
    int e = blockIdx.x * blockDim.x + threadIdx.x;
    if (e >= N_EDGES) return;
    int s = __ldg(srcp + e);
    int d = __ldg(dstp + e);
    const float4* ewp = reinterpret_cast<const float4*>(&g_ew[(size_t)e * CH]);
    const float4* hp  = reinterpret_cast<const float4*>(&g_h[s * CH]);
    float4* pp = reinterpret_cast<float4*>(&g_partial[d * CH]);
#pragma unroll
    for (int i = 0; i < 4; i++) {
        float4 w = __ldcs(ewp + i);
        float4 h = __ldg(hp + i);
        red_add_v4(pp + i, make_float4(w.x * h.x, w.y * h.y, w.z * h.z, w.w * h.w));
    }
}

// ---------- layer-1 finish: h = relu(dinv*(partial+hs1)+b1); hs2 = dinv*(h@W2); partial=0 ----------
__global__ void __launch_bounds__(256) k_layer1_finish(
        const float* __restrict__ b1, const float* __restrict__ W2) {
    __shared__ float W2s[CH * CH];
    __shared__ float b1s[CH];
    if (threadIdx.x < CH * CH) W2s[threadIdx.x] = W2[threadIdx.x];
    if (threadIdx.x < CH) b1s[threadIdx.x] = b1[threadIdx.x];
    __syncthreads();
    int n = blockIdx.x * blockDim.x + threadIdx.x;
    if (n >= N_NODES) return;
    float h[CH], dv[CH];
    const float4* d4p = reinterpret_cast<const float4*>(&g_dinv[n * CH]);
    const float4* p4p = reinterpret_cast<const float4*>(&g_partial[n * CH]);
    float4* h4p = reinterpret_cast<float4*>(&g_h[n * CH]);
#pragma unroll
    for (int i = 0; i < 4; i++) {
        float4 d4 = d4p[i];
        float4 p4 = p4p[i];
        float4 s4 = h4p[i];  // hs1
        dv[4 * i + 0] = d4.x; dv[4 * i + 1] = d4.y; dv[4 * i + 2] = d4.z; dv[4 * i + 3] = d4.w;
        h[4 * i + 0] = fmaxf(d4.x * (p4.x + s4.x) + b1s[4 * i + 0], 0.f);
        h[4 * i + 1] = fmaxf(d4.y * (p4.y + s4.y) + b1s[4 * i + 1], 0.f);
        h[4 * i + 2] = fmaxf(d4.z * (p4.z + s4.z) + b1s[4 * i + 2], 0.f);
        h[4 * i + 3] = fmaxf(d4.w * (p4.w + s4.w) + b1s[4 * i + 3], 0.f);
    }
    float acc[CH];
#pragma unroll
    for (int j = 0; j < CH; j++) acc[j] = 0.f;
#pragma unroll
    for (int k = 0; k < CH; k++) {
        float hk = h[k];
#pragma unroll
        for (int j = 0; j < CH; j++) acc[j] = fmaf(hk, W2s[k * CH + j], acc[j]);
    }
    float4* pz = reinterpret_cast<float4*>(&g_partial[n * CH]);
    float4 zero = make_float4(0.f, 0.f, 0.f, 0.f);
#pragma unroll
    for (int i = 0; i < 4; i++) {
        h4p[i] = make_float4(dv[4 * i + 0] * acc[4 * i + 0],
                             dv[4 * i + 1] * acc[4 * i + 1],
                             dv[4 * i + 2] * acc[4 * i + 2],
                             dv[4 * i + 3] * acc[4 * i + 3]);  // hs2
        pz[i] = zero;
    }
}

// ---------- out = dinv*(partial + hs2) + b2 ----------
__global__ void __launch_bounds__(256) k_out(
        const float* __restrict__ b2, float* __restrict__ out) {
    int n = blockIdx.x * blockDim.x + threadIdx.x;
    if (n >= N_NODES) return;
    float4* o4 = reinterpret_cast<float4*>(out);
    const float4* d4p = reinterpret_cast<const float4*>(&g_dinv[n * CH]);
    const float4* p4p = reinterpret_cast<const float4*>(&g_partial[n * CH]);
    const float4* s4p = reinterpret_cast<const float4*>(&g_h[n * CH]);
#pragma unroll
    for (int i = 0; i < 4; i++) {
        float4 d4 = d4p[i];
        float4 p4 = p4p[i];
        float4 s4 = s4p[i];
        float4 o;
        o.x = d4.x * (p4.x + s4.x) + __ldg(b2 + 4 * i + 0);
        o.y = d4.y * (p4.y + s4.y) + __ldg(b2 + 4 * i + 1);
        o.z = d4.z * (p4.z + s4.z) + __ldg(b2 + 4 * i + 2);
        o.w = d4.w * (p4.w + s4.w) + __ldg(b2 + 4 * i + 3);
        o4[n * 4 + i] = o;
    }
}

extern "C" void kernel_launch(void* const* d_in, const int* in_sizes, int n_in,
                              void* d_out, int out_size) {
    const float* x  = (const float*)d_in[0];
    const int*   ei = (const int*)d_in[1];
    const float* ea = (const float*)d_in[2];
    const float* We = (const float*)d_in[3];
    const float* be = (const float*)d_in[4];
    const float* W1 = (const float*)d_in[5];
    const float* b1 = (const float*)d_in[6];
    const float* W2 = (const float*)d_in[7];
    const float* b2 = (const float*)d_in[8];
    const int* srcp = ei;
    const int* dstp = ei + N_EDGES;
    float* out = (float*)d_out;

    const int nb_n  = (N_NODES + 255) / 256;
    const int nb_e  = (N_EDGES + 255) / 256;
    const int nb_nc = (N_NODES * CH + 127) / 128;
    const int nb_s  = (N_NODES + 63) / 64;

    k_zero_cnt      <<<nb_n, 256>>>();
    k_ew_hist       <<<nb_e, 256>>>(ea, We, be, dstp);  // ew (bit-contract) + histogram
    k_scan_block    <<<NB_SCAN, 256>>>();
    k_scan_tot      <<<1, 512>>>();
    k_scan_add      <<<nb_n, 256>>>();
    k_fill          <<<nb_e, 256>>>(dstp);
    k_sort          <<<nb_s, 64>>>();                   // smem-staged insertion sort
    k_xw            <<<nb_n, 256>>>(x, W1);
    k_deg_dinv_hs1  <<<nb_nc, 128>>>();                 // bit-contract sequential deg
    k_edge_scatter  <<<nb_e, 256>>>(srcp, dstp);
    k_layer1_finish <<<nb_n, 256>>>(b1, W2);
    k_edge_scatter  <<<nb_e, 256>>>(srcp, dstp);
    k_out           <<<nb_n, 256>>>(b2, out);
}

// round 14
// speedup vs baseline: 1.0210x; 1.0209x over previous
#include <cuda_runtime.h>

#define N_NODES 100000
#define N_EDGES 3200000
#define CH      16
#define INC     128
#define NB_SCAN 391   // ceil(N_NODES/256)

// Scratch (static __device__ arrays — allocation-free per harness rules)
static __device__ __align__(16) float g_ew[(size_t)N_EDGES * CH];   // [E,16]
static __device__ __align__(16) float g_dinv[N_NODES * CH];
static __device__ __align__(16) float g_h[N_NODES * CH];            // h1lin->hs1->hs2
static __device__ __align__(16) float g_partial[N_NODES * CH];
static __device__ int g_cnt[N_NODES];
static __device__ int g_rowptr[N_NODES + 1];
static __device__ int g_bsum[512];
static __device__ int g_boff[512];
static __device__ int g_cursor[N_NODES];
static __device__ int g_elist[N_EDGES];

__device__ __forceinline__ void red_add_v4(float4* addr, float4 v) {
    asm volatile("red.global.add.v4.f32 [%0], {%1, %2, %3, %4};"
                 :: "l"(addr), "f"(v.x), "f"(v.y), "f"(v.z), "f"(v.w)
                 : "memory");
}

// ---------- CSR build ----------
__global__ void k_zero_cnt(void) {
    int i = blockIdx.x * blockDim.x + threadIdx.x;
    if (i < N_NODES) g_cnt[i] = 0;
}

// ---------- ew = edge_attr @ We + be  (+ fused dst histogram) ----------
// BIT-CONTRACT (matches reference, do not change semantics): aarch64
// NEON-style k-vectorized dot, 4 FUSED lane accumulators (lane = k mod 4)
// over ascending k-groups, pairwise combine (l0+l1)+(l2+l3), bias last.
// R14: lane accumulators widened to per-j arrays so Ws loads become uniform
// LDS.128 broadcasts — per-chain operation sequence is IDENTICAL (bit-exact).
__global__ void __launch_bounds__(256) k_ew_hist(
        const float* __restrict__ ea, const float* __restrict__ We,
        const float* __restrict__ be, const int* __restrict__ dstp) {
    __shared__ __align__(16) float Ws[CH * CH];
    __shared__ float bs[CH];
    if (threadIdx.x < CH * CH) Ws[threadIdx.x] = We[threadIdx.x];
    if (threadIdx.x < CH) bs[threadIdx.x] = be[threadIdx.x];
    __syncthreads();
    int e = blockIdx.x * blockDim.x + threadIdx.x;
    if (e >= N_EDGES) return;
    const float4* ear = reinterpret_cast<const float4*>(ea) + (size_t)e * 4;
    float4 a0 = __ldcs(ear + 0), a1 = __ldcs(ear + 1);
    float4 a2 = __ldcs(ear + 2), a3 = __ldcs(ear + 3);
    float av[CH] = {a0.x, a0.y, a0.z, a0.w, a1.x, a1.y, a1.z, a1.w,
                    a2.x, a2.y, a2.z, a2.w, a3.x, a3.y, a3.z, a3.w};
    float acc0[CH], acc1[CH], acc2[CH], acc3[CH];
#pragma unroll
    for (int j = 0; j < CH; j++) { acc0[j] = acc1[j] = acc2[j] = acc3[j] = 0.f; }

#define EW_LANE(ACC, K)                                                        \
    do {                                                                       \
        float a_ = av[(K)];                                                    \
        const float4* wr_ = reinterpret_cast<const float4*>(&Ws[(K) * CH]);    \
        float4 q0_ = wr_[0], q1_ = wr_[1], q2_ = wr_[2], q3_ = wr_[3];         \
        ACC[0]  = fmaf(a_, q0_.x, ACC[0]);  ACC[1]  = fmaf(a_, q0_.y, ACC[1]); \
        ACC[2]  = fmaf(a_, q0_.z, ACC[2]);  ACC[3]  = fmaf(a_, q0_.w, ACC[3]); \
        ACC[4]  = fmaf(a_, q1_.x, ACC[4]);  ACC[5]  = fmaf(a_, q1_.y, ACC[5]); \
        ACC[6]  = fmaf(a_, q1_.z, ACC[6]);  ACC[7]  = fmaf(a_, q1_.w, ACC[7]); \
        ACC[8]  = fmaf(a_, q2_.x, ACC[8]);  ACC[9]  = fmaf(a_, q2_.y, ACC[9]); \
        ACC[10] = fmaf(a_, q2_.z, ACC[10]); ACC[11] = fmaf(a_, q2_.w, ACC[11]);\
        ACC[12] = fmaf(a_, q3_.x, ACC[12]); ACC[13] = fmaf(a_, q3_.y, ACC[13]);\
        ACC[14] = fmaf(a_, q3_.z, ACC[14]); ACC[15] = fmaf(a_, q3_.w, ACC[15]);\
    } while (0)

#pragma unroll
    for (int g = 0; g < 4; g++) {
        EW_LANE(acc0, 4 * g + 0);
        EW_LANE(acc1, 4 * g + 1);
        EW_LANE(acc2, 4 * g + 2);
        EW_LANE(acc3, 4 * g + 3);
    }
#undef EW_LANE

    float w[CH];
#pragma unroll
    for (int j = 0; j < CH; j++) {
        float s01 = __fadd_rn(acc0[j], acc1[j]);
        float s23 = __fadd_rn(acc2[j], acc3[j]);
        w[j] = __fadd_rn(__fadd_rn(s01, s23), bs[j]);
    }
    float4* ewp = reinterpret_cast<float4*>(&g_ew[(size_t)e * CH]);
    __stcs(ewp + 0, make_float4(w[0],  w[1],  w[2],  w[3]));
    __stcs(ewp + 1, make_float4(w[4],  w[5],  w[6],  w[7]));
    __stcs(ewp + 2, make_float4(w[8],  w[9],  w[10], w[11]));
    __stcs(ewp + 3, make_float4(w[12], w[13], w[14], w[15]));
    atomicAdd(&g_cnt[__ldg(dstp + e)], 1);   // fused histogram
}

__global__ void k_scan_block(void) {
    __shared__ int s[256];
    int i = blockIdx.x * 256 + threadIdx.x;
    int v = (i < N_NODES) ? g_cnt[i] : 0;
    s[threadIdx.x] = v;
    __syncthreads();
#pragma unroll
    for (int off = 1; off < 256; off <<= 1) {
        int t = (threadIdx.x >= off) ? s[threadIdx.x - off] : 0;
        __syncthreads();
        s[threadIdx.x] += t;
        __syncthreads();
    }
    if (i < N_NODES) g_rowptr[i] = s[threadIdx.x] - v;  // exclusive within block
    if (threadIdx.x == 255) g_bsum[blockIdx.x] = s[255];
}

__global__ void k_scan_tot(void) {
    __shared__ int s[512];
    int tid = threadIdx.x;
    int v = (tid < NB_SCAN) ? g_bsum[tid] : 0;
    s[tid] = v;
    __syncthreads();
#pragma unroll
    for (int off = 1; off < 512; off <<= 1) {
        int t = (tid >= off) ? s[tid - off] : 0;
        __syncthreads();
        s[tid] += t;
        __syncthreads();
    }
    g_boff[tid] = s[tid] - v;  // exclusive
}

__global__ void k_scan_add(void) {
    int i = blockIdx.x * blockDim.x + threadIdx.x;
    if (i < N_NODES) {
        g_rowptr[i] += g_boff[i >> 8];
        g_cursor[i] = 0;
    }
    if (i == 0) g_rowptr[N_NODES] = N_EDGES;
}

__global__ void k_fill(const int* __restrict__ dstp) {
    int e = blockIdx.x * blockDim.x + threadIdx.x;
    if (e >= N_EDGES) return;
    int d = dstp[e];
    int pos = g_rowptr[d] + atomicAdd(&g_cursor[d], 1);
    g_elist[pos] = e;
}

// Per-node ascending sort of edge ids — staged in shared memory.
__global__ void __launch_bounds__(64) k_sort(void) {
    __shared__ int buf[64][97];
    int n = blockIdx.x * 64 + threadIdx.x;
    if (n >= N_NODES) return;
    int lo = g_rowptr[n], hi = g_rowptr[n + 1];
    int L = hi - lo;
    if (L <= 96) {
        int* b = buf[threadIdx.x];
        for (int i = 0; i < L; i++) b[i] = g_elist[lo + i];
        for (int i = 1; i < L; i++) {
            int v = b[i];
            int j = i - 1;
            while (j >= 0 && b[j] > v) { b[j + 1] = b[j]; j--; }
            b[j + 1] = v;
        }
        for (int i = 0; i < L; i++) g_elist[lo + i] = b[i];
    } else {
        for (int i = lo + 1; i < hi; i++) {
            int v = g_elist[i];
            int j = i - 1;
            while (j >= lo && g_elist[j] > v) { g_elist[j + 1] = g_elist[j]; j--; }
            g_elist[j + 1] = v;
        }
    }
}

// ---------- h1lin = x @ W1 (fp32; non-amplified) ----------
__global__ void __launch_bounds__(256) k_xw(
        const float* __restrict__ x, const float* __restrict__ W1) {
    __shared__ float W1s[INC * CH];
    for (int i = threadIdx.x; i < INC * CH; i += blockDim.x) W1s[i] = W1[i];
    __syncthreads();
    int n = blockIdx.x * blockDim.x + threadIdx.x;
    if (n >= N_NODES) return;
    float acc[CH];
#pragma unroll
    for (int j = 0; j < CH; j++) acc[j] = 0.f;
    const float4* xr = reinterpret_cast<const float4*>(x) + (size_t)n * (INC / 4);
#pragma unroll 4
    for (int k4 = 0; k4 < INC / 4; k4++) {
        float4 xv = __ldg(xr + k4);
        const float* w0 = &W1s[(k4 * 4 + 0) * CH];
        const float* w1 = &W1s[(k4 * 4 + 1) * CH];
        const float* w2 = &W1s[(k4 * 4 + 2) * CH];
        const float* w3 = &W1s[(k4 * 4 + 3) * CH];
#pragma unroll
        for (int j = 0; j < CH; j++) {
            acc[j] = fmaf(xv.x, w0[j], acc[j]);
            acc[j] = fmaf(xv.y, w1[j], acc[j]);
            acc[j] = fmaf(xv.z, w2[j], acc[j]);
            acc[j] = fmaf(xv.w, w3[j], acc[j]);
        }
    }
    float4* hp = reinterpret_cast<float4*>(&g_h[n * CH]);
#pragma unroll
    for (int i = 0; i < 4; i++)
        hp[i] = make_float4(acc[4 * i], acc[4 * i + 1], acc[4 * i + 2], acc[4 * i + 3]);
}

// ---------- deg: BIT-CONTRACT sequential ascending-e fp32 sum, +1.0 last ----------
__global__ void __launch_bounds__(128) k_deg_dinv_hs1(void) {
    int t = blockIdx.x * blockDim.x + threadIdx.x;
    int n = t >> 4;
    int c = t & 15;
    if (n >= N_NODES) return;
    int lo = g_rowptr[n], hi = g_rowptr[n + 1];
    float acc = 0.f;
    for (int i = lo; i < hi; i++) {
        int e = g_elist[i];
        acc = __fadd_rn(acc, __ldg(&g_ew[(size_t)e * CH + c]));
    }
    float deg = __fadd_rn(acc, 1.0f);
    float dinv = 0.f;
    if (deg > 0.f) {
        double dd = (double)fabsf(deg) + 1e-12;
        dinv = (float)(1.0 / sqrt(dd));
    }
    int idx = n * CH + c;
    g_dinv[idx] = dinv;
    g_h[idx] = dinv * g_h[idx];  // hs1
    g_partial[idx] = 0.f;
}

// ---------- edge scatter: partial[dst] += ew * hs[src]  (ILP=2) ----------
__global__ void __launch_bounds__(256) k_edge_scatter(
        const int* __restrict__ srcp, const int* __restrict__ dstp) {
    int e0 = blockIdx.x * 512 + threadIdx.x;
    int e1 = e0 + 256;
    // 3.2M = 512*6250 exactly — no bounds checks needed for this grid.
    int s0 = __ldg(srcp + e0), d0 = __ldg(dstp + e0);
    int s1 = __ldg(srcp + e1), d1 = __ldg(dstp + e1);
    const float4* ew0 = reinterpret_cast<const float4*>(&g_ew[(size_t)e0 * CH]);
    const float4* ew1 = reinterpret_cast<const float4*>(&g_ew[(size_t)e1 * CH]);
    const float4* h0  = reinterpret_cast<const float4*>(&g_h[s0 * CH]);
    const float4* h1  = reinterpret_cast<const float4*>(&g_h[s1 * CH]);
    float4 w00 = __ldcs(ew0 + 0), w01 = __ldcs(ew0 + 1), w02 = __ldcs(ew0 + 2), w03 = __ldcs(ew0 + 3);
    float4 w10 = __ldcs(ew1 + 0), w11 = __ldcs(ew1 + 1), w12 = __ldcs(ew1 + 2), w13 = __ldcs(ew1 + 3);
    float4 v00 = __ldg(h0 + 0), v01 = __ldg(h0 + 1), v02 = __ldg(h0 + 2), v03 = __ldg(h0 + 3);
    float4 v10 = __ldg(h1 + 0), v11 = __ldg(h1 + 1), v12 = __ldg(h1 + 2), v13 = __ldg(h1 + 3);
    float4* p0 = reinterpret_cast<float4*>(&g_partial[d0 * CH]);
    float4* p1 = reinterpret_cast<float4*>(&g_partial[d1 * CH]);
    red_add_v4(p0 + 0, make_float4(w00.x * v00.x, w00.y * v00.y, w00.z * v00.z, w00.w * v00.w));
    red_add_v4(p0 + 1, make_float4(w01.x * v01.x, w01.y * v01.y, w01.z * v01.z, w01.w * v01.w));
    red_add_v4(p0 + 2, make_float4(w02.x * v02.x, w02.y * v02.y, w02.z * v02.z, w02.w * v02.w));
    red_add_v4(p0 + 3, make_float4(w03.x * v03.x, w03.y * v03.y, w03.z * v03.z, w03.w * v03.w));
    red_add_v4(p1 + 0, make_float4(w10.x * v10.x, w10.y * v10.y, w10.z * v10.z, w10.w * v10.w));
    red_add_v4(p1 + 1, make_float4(w11.x * v11.x, w11.y * v11.y, w11.z * v11.z, w11.w * v11.w));
    red_add_v4(p1 + 2, make_float4(w12.x * v12.x, w12.y * v12.y, w12.z * v12.z, w12.w * v12.w));
    red_add_v4(p1 + 3, make_float4(w13.x * v13.x, w13.y * v13.y, w13.z * v13.z, w13.w * v13.w));
}

// ---------- layer-1 finish: h = relu(dinv*(partial+hs1)+b1); hs2 = dinv*(h@W2); partial=0 ----------
__global__ void __launch_bounds__(256) k_layer1_finish(
        const float* __restrict__ b1, const float* __restrict__ W2) {
    __shared__ float W2s[CH * CH];
    __shared__ float b1s[CH];
    if (threadIdx.x < CH * CH) W2s[threadIdx.x] = W2[threadIdx.x];
    if (threadIdx.x < CH) b1s[threadIdx.x] = b1[threadIdx.x];
    __syncthreads();
    int n = blockIdx.x * blockDim.x + threadIdx.x;
    if (n >= N_NODES) return;
    float h[CH], dv[CH];
    const float4* d4p = reinterpret_cast<const float4*>(&g_dinv[n * CH]);
    const float4* p4p = reinterpret_cast<const float4*>(&g_partial[n * CH]);
    float4* h4p = reinterpret_cast<float4*>(&g_h[n * CH]);
#pragma unroll
    for (int i = 0; i < 4; i++) {
        float4 d4 = d4p[i];
        float4 p4 = p4p[i];
        float4 s4 = h4p[i];  // hs1
        dv[4 * i + 0] = d4.x; dv[4 * i + 1] = d4.y; dv[4 * i + 2] = d4.z; dv[4 * i + 3] = d4.w;
        h[4 * i + 0] = fmaxf(d4.x * (p4.x + s4.x) + b1s[4 * i + 0], 0.f);
        h[4 * i + 1] = fmaxf(d4.y * (p4.y + s4.y) + b1s[4 * i + 1], 0.f);
        h[4 * i + 2] = fmaxf(d4.z * (p4.z + s4.z) + b1s[4 * i + 2], 0.f);
        h[4 * i + 3] = fmaxf(d4.w * (p4.w + s4.w) + b1s[4 * i + 3], 0.f);
    }
    float acc[CH];
#pragma unroll
    for (int j = 0; j < CH; j++) acc[j] = 0.f;
#pragma unroll
    for (int k = 0; k < CH; k++) {
        float hk = h[k];
#pragma unroll
        for (int j = 0; j < CH; j++) acc[j] = fmaf(hk, W2s[k * CH + j], acc[j]);
    }
    float4* pz = reinterpret_cast<float4*>(&g_partial[n * CH]);
    float4 zero = make_float4(0.f, 0.f, 0.f, 0.f);
#pragma unroll
    for (int i = 0; i < 4; i++) {
        h4p[i] = make_float4(dv[4 * i + 0] * acc[4 * i + 0],
                             dv[4 * i + 1] * acc[4 * i + 1],
                             dv[4 * i + 2] * acc[4 * i + 2],
                             dv[4 * i + 3] * acc[4 * i + 3]);  // hs2
        pz[i] = zero;
    }
}

// ---------- out = dinv*(partial + hs2) + b2 ----------
__global__ void __launch_bounds__(256) k_out(
        const float* __restrict__ b2, float* __restrict__ out) {
    int n = blockIdx.x * blockDim.x + threadIdx.x;
    if (n >= N_NODES) return;
    float4* o4 = reinterpret_cast<float4*>(out);
    const float4* d4p = reinterpret_cast<const float4*>(&g_dinv[n * CH]);
    const float4* p4p = reinterpret_cast<const float4*>(&g_partial[n * CH]);
    const float4* s4p = reinterpret_cast<const float4*>(&g_h[n * CH]);
#pragma unroll
    for (int i = 0; i < 4; i++) {
        float4 d4 = d4p[i];
        float4 p4 = p4p[i];
        float4 s4 = s4p[i];
        float4 o;
        o.x = d4.x * (p4.x + s4.x) + __ldg(b2 + 4 * i + 0);
        o.y = d4.y * (p4.y + s4.y) + __ldg(b2 + 4 * i + 1);
        o.z = d4.z * (p4.z + s4.z) + __ldg(b2 + 4 * i + 2);
        o.w = d4.w * (p4.w + s4.w) + __ldg(b2 + 4 * i + 3);
        o4[n * 4 + i] = o;
    }
}

extern "C" void kernel_launch(void* const* d_in, const int* in_sizes, int n_in,
                              void* d_out, int out_size) {
    const float* x  = (const float*)d_in[0];
    const int*   ei = (const int*)d_in[1];
    const float* ea = (const float*)d_in[2];
    const float* We = (const float*)d_in[3];
    const float* be = (const float*)d_in[4];
    const float* W1 = (const float*)d_in[5];
    const float* b1 = (const float*)d_in[6];
    const float* W2 = (const float*)d_in[7];
    const float* b2 = (const float*)d_in[8];
    const int* srcp = ei;
    const int* dstp = ei + N_EDGES;
    float* out = (float*)d_out;

    const int nb_n  = (N_NODES + 255) / 256;
    const int nb_e  = (N_EDGES + 255) / 256;
    const int nb_e2 = N_EDGES / 512;                    // 6250, exact
    const int nb_nc = (N_NODES * CH + 127) / 128;
    const int nb_s  = (N_NODES + 63) / 64;

    k_zero_cnt      <<<nb_n, 256>>>();
    k_ew_hist       <<<nb_e, 256>>>(ea, We, be, dstp);  // ew (bit-contract) + histogram
    k_scan_block    <<<NB_SCAN, 256>>>();
    k_scan_tot      <<<1, 512>>>();
    k_scan_add      <<<nb_n, 256>>>();
    k_fill          <<<nb_e, 256>>>(dstp);
    k_sort          <<<nb_s, 64>>>();
    k_xw            <<<nb_n, 256>>>(x, W1);
    k_deg_dinv_hs1  <<<nb_nc, 128>>>();                 // bit-contract sequential deg
    k_edge_scatter  <<<nb_e2, 256>>>(srcp, dstp);
    k_layer1_finish <<<nb_n, 256>>>(b1, W2);
    k_edge_scatter  <<<nb_e2, 256>>>(srcp, dstp);
    k_out           <<<nb_n, 256>>>(b2, out);
}

// round 15
// speedup vs baseline: 1.1056x; 1.0828x over previous
#include <cuda_runtime.h>

#define N_NODES 100000
#define N_EDGES 3200000
#define CH      16
#define INC     128
#define NB_SCAN 391   // ceil(N_NODES/256)

// Scratch (static __device__ arrays — allocation-free per harness rules)
static __device__ __align__(16) float g_ew[(size_t)N_EDGES * CH];   // [E,16]
static __device__ __align__(16) float g_dinv[N_NODES * CH];
static __device__ __align__(16) float g_h[N_NODES * CH];            // h1lin->hs1->hs2
static __device__ __align__(16) float g_partial[N_NODES * CH];
static __device__ int g_cnt[N_NODES];
static __device__ int g_rowptr[N_NODES + 1];
static __device__ int g_bsum[512];
static __device__ int g_boff[512];
static __device__ int g_cursor[N_NODES];
static __device__ int g_elist[N_EDGES];

// ---------- CSR build ----------
__global__ void k_zero_cnt(void) {
    int i = blockIdx.x * blockDim.x + threadIdx.x;
    if (i < N_NODES) g_cnt[i] = 0;
}

// ---------- ew = edge_attr @ We + be  (+ fused dst histogram) ----------
// BIT-CONTRACT (matches reference): 4 FUSED lane accumulators (lane = k mod 4)
// over ascending k-groups, pairwise combine (l0+l1)+(l2+l3), bias last.
// R15: weights TRANSPOSED in smem so each output j needs 4 LDS.128 and only
// 4 live accumulators — per-chain op sequence identical (bit-exact).
__global__ void __launch_bounds__(256) k_ew_hist(
        const float* __restrict__ ea, const float* __restrict__ We,
        const float* __restrict__ be, const int* __restrict__ dstp) {
    __shared__ __align__(16) float Wt[CH * CH];   // Wt[j*16+k] = We[k*16+j]
    __shared__ float bs[CH];
    if (threadIdx.x < CH * CH) {
        int k = threadIdx.x / CH, j = threadIdx.x % CH;
        Wt[j * CH + k] = We[threadIdx.x];
    }
    if (threadIdx.x < CH) bs[threadIdx.x] = be[threadIdx.x];
    __syncthreads();
    int e = blockIdx.x * blockDim.x + threadIdx.x;
    if (e >= N_EDGES) return;
    const float4* ear = reinterpret_cast<const float4*>(ea) + (size_t)e * 4;
    float4 a0 = __ldcs(ear + 0), a1 = __ldcs(ear + 1);
    float4 a2 = __ldcs(ear + 2), a3 = __ldcs(ear + 3);
    float av[CH] = {a0.x, a0.y, a0.z, a0.w, a1.x, a1.y, a1.z, a1.w,
                    a2.x, a2.y, a2.z, a2.w, a3.x, a3.y, a3.z, a3.w};
    float w[CH];
#pragma unroll
    for (int j = 0; j < CH; j++) {
        const float4* wr = reinterpret_cast<const float4*>(&Wt[j * CH]);
        float4 q0 = wr[0], q1 = wr[1], q2 = wr[2], q3 = wr[3];
        float acc0 = 0.f, acc1 = 0.f, acc2 = 0.f, acc3 = 0.f;
        acc0 = fmaf(av[0],  q0.x, acc0);  acc1 = fmaf(av[1],  q0.y, acc1);
        acc2 = fmaf(av[2],  q0.z, acc2);  acc3 = fmaf(av[3],  q0.w, acc3);
        acc0 = fmaf(av[4],  q1.x, acc0);  acc1 = fmaf(av[5],  q1.y, acc1);
        acc2 = fmaf(av[6],  q1.z, acc2);  acc3 = fmaf(av[7],  q1.w, acc3);
        acc0 = fmaf(av[8],  q2.x, acc0);  acc1 = fmaf(av[9],  q2.y, acc1);
        acc2 = fmaf(av[10], q2.z, acc2);  acc3 = fmaf(av[11], q2.w, acc3);
        acc0 = fmaf(av[12], q3.x, acc0);  acc1 = fmaf(av[13], q3.y, acc1);
        acc2 = fmaf(av[14], q3.z, acc2);  acc3 = fmaf(av[15], q3.w, acc3);
        float s01 = __fadd_rn(acc0, acc1);
        float s23 = __fadd_rn(acc2, acc3);
        w[j] = __fadd_rn(__fadd_rn(s01, s23), bs[j]);
    }
    float4* ewp = reinterpret_cast<float4*>(&g_ew[(size_t)e * CH]);
    __stcs(ewp + 0, make_float4(w[0],  w[1],  w[2],  w[3]));
    __stcs(ewp + 1, make_float4(w[4],  w[5],  w[6],  w[7]));
    __stcs(ewp + 2, make_float4(w[8],  w[9],  w[10], w[11]));
    __stcs(ewp + 3, make_float4(w[12], w[13], w[14], w[15]));
    atomicAdd(&g_cnt[__ldg(dstp + e)], 1);   // fused histogram
}

__global__ void k_scan_block(void) {
    __shared__ int s[256];
    int i = blockIdx.x * 256 + threadIdx.x;
    int v = (i < N_NODES) ? g_cnt[i] : 0;
    s[threadIdx.x] = v;
    __syncthreads();
#pragma unroll
    for (int off = 1; off < 256; off <<= 1) {
        int t = (threadIdx.x >= off) ? s[threadIdx.x - off] : 0;
        __syncthreads();
        s[threadIdx.x] += t;
        __syncthreads();
    }
    if (i < N_NODES) g_rowptr[i] = s[threadIdx.x] - v;  // exclusive within block
    if (threadIdx.x == 255) g_bsum[blockIdx.x] = s[255];
}

__global__ void k_scan_tot(void) {
    __shared__ int s[512];
    int tid = threadIdx.x;
    int v = (tid < NB_SCAN) ? g_bsum[tid] : 0;
    s[tid] = v;
    __syncthreads();
#pragma unroll
    for (int off = 1; off < 512; off <<= 1) {
        int t = (tid >= off) ? s[tid - off] : 0;
        __syncthreads();
        s[tid] += t;
        __syncthreads();
    }
    g_boff[tid] = s[tid] - v;  // exclusive
}

__global__ void k_scan_add(void) {
    int i = blockIdx.x * blockDim.x + threadIdx.x;
    if (i < N_NODES) {
        g_rowptr[i] += g_boff[i >> 8];
        g_cursor[i] = 0;
    }
    if (i == 0) g_rowptr[N_NODES] = N_EDGES;
}

__global__ void k_fill(const int* __restrict__ dstp) {
    int e = blockIdx.x * blockDim.x + threadIdx.x;
    if (e >= N_EDGES) return;
    int d = dstp[e];
    int pos = g_rowptr[d] + atomicAdd(&g_cursor[d], 1);
    g_elist[pos] = e;
}

// Per-node ascending sort of edge ids — staged in shared memory.
__global__ void __launch_bounds__(64) k_sort(void) {
    __shared__ int buf[64][97];
    int n = blockIdx.x * 64 + threadIdx.x;
    if (n >= N_NODES) return;
    int lo = g_rowptr[n], hi = g_rowptr[n + 1];
    int L = hi - lo;
    if (L <= 96) {
        int* b = buf[threadIdx.x];
        for (int i = 0; i < L; i++) b[i] = g_elist[lo + i];
        for (int i = 1; i < L; i++) {
            int v = b[i];
            int j = i - 1;
            while (j >= 0 && b[j] > v) { b[j + 1] = b[j]; j--; }
            b[j + 1] = v;
        }
        for (int i = 0; i < L; i++) g_elist[lo + i] = b[i];
    } else {
        for (int i = lo + 1; i < hi; i++) {
            int v = g_elist[i];
            int j = i - 1;
            while (j >= lo && g_elist[j] > v) { g_elist[j + 1] = g_elist[j]; j--; }
            g_elist[j + 1] = v;
        }
    }
}

// ---------- h1lin = x @ W1 (fp32; non-amplified) ----------
__global__ void __launch_bounds__(256) k_xw(
        const float* __restrict__ x, const float* __restrict__ W1) {
    __shared__ float W1s[INC * CH];
    for (int i = threadIdx.x; i < INC * CH; i += blockDim.x) W1s[i] = W1[i];
    __syncthreads();
    int n = blockIdx.x * blockDim.x + threadIdx.x;
    if (n >= N_NODES) return;
    float acc[CH];
#pragma unroll
    for (int j = 0; j < CH; j++) acc[j] = 0.f;
    const float4* xr = reinterpret_cast<const float4*>(x) + (size_t)n * (INC / 4);
#pragma unroll 4
    for (int k4 = 0; k4 < INC / 4; k4++) {
        float4 xv = __ldg(xr + k4);
        const float* w0 = &W1s[(k4 * 4 + 0) * CH];
        const float* w1 = &W1s[(k4 * 4 + 1) * CH];
        const float* w2 = &W1s[(k4 * 4 + 2) * CH];
        const float* w3 = &W1s[(k4 * 4 + 3) * CH];
#pragma unroll
        for (int j = 0; j < CH; j++) {
            acc[j] = fmaf(xv.x, w0[j], acc[j]);
            acc[j] = fmaf(xv.y, w1[j], acc[j]);
            acc[j] = fmaf(xv.z, w2[j], acc[j]);
            acc[j] = fmaf(xv.w, w3[j], acc[j]);
        }
    }
    float4* hp = reinterpret_cast<float4*>(&g_h[n * CH]);
#pragma unroll
    for (int i = 0; i < 4; i++)
        hp[i] = make_float4(acc[4 * i], acc[4 * i + 1], acc[4 * i + 2], acc[4 * i + 3]);
}

// ---------- deg: BIT-CONTRACT sequential ascending-e fp32 sum, +1.0 last ----------
__global__ void __launch_bounds__(128) k_deg_dinv_hs1(void) {
    int t = blockIdx.x * blockDim.x + threadIdx.x;
    int n = t >> 4;
    int c = t & 15;
    if (n >= N_NODES) return;
    int lo = g_rowptr[n], hi = g_rowptr[n + 1];
    float acc = 0.f;
    for (int i = lo; i < hi; i++) {
        int e = g_elist[i];
        acc = __fadd_rn(acc, __ldg(&g_ew[(size_t)e * CH + c]));
    }
    float deg = __fadd_rn(acc, 1.0f);
    float dinv = 0.f;
    if (deg > 0.f) {
        double dd = (double)fabsf(deg) + 1e-12;
        dinv = (float)(1.0 / sqrt(dd));
    }
    int idx = n * CH + c;
    g_dinv[idx] = dinv;
    g_h[idx] = dinv * g_h[idx];  // hs1
}

// ---------- layer aggregation as CSR GATHER (no atomics): ----------
// partial[n,c] = Σ_{e in CSR[n]} ew[e,c] * hs[src[e],c]   (ascending order)
__global__ void __launch_bounds__(128) k_gather(const int* __restrict__ srcp) {
    int t = blockIdx.x * blockDim.x + threadIdx.x;
    int n = t >> 4;
    int c = t & 15;
    if (n >= N_NODES) return;
    int lo = g_rowptr[n], hi = g_rowptr[n + 1];
    float acc = 0.f;
    for (int i = lo; i < hi; i++) {
        int e = __ldg(&g_elist[i]);
        int s = __ldg(srcp + e);
        float w = __ldg(&g_ew[(size_t)e * CH + c]);
        float h = __ldg(&g_h[s * CH + c]);
        acc = fmaf(w, h, acc);
    }
    g_partial[n * CH + c] = acc;   // plain store — no atomics, no pre-zero
}

// ---------- layer-1 finish: h = relu(dinv*(partial+hs1)+b1); hs2 = dinv*(h@W2) ----------
__global__ void __launch_bounds__(256) k_layer1_finish(
        const float* __restrict__ b1, const float* __restrict__ W2) {
    __shared__ float W2s[CH * CH];
    __shared__ float b1s[CH];
    if (threadIdx.x < CH * CH) W2s[threadIdx.x] = W2[threadIdx.x];
    if (threadIdx.x < CH) b1s[threadIdx.x] = b1[threadIdx.x];
    __syncthreads();
    int n = blockIdx.x * blockDim.x + threadIdx.x;
    if (n >= N_NODES) return;
    float h[CH], dv[CH];
    const float4* d4p = reinterpret_cast<const float4*>(&g_dinv[n * CH]);
    const float4* p4p = reinterpret_cast<const float4*>(&g_partial[n * CH]);
    float4* h4p = reinterpret_cast<float4*>(&g_h[n * CH]);
#pragma unroll
    for (int i = 0; i < 4; i++) {
        float4 d4 = d4p[i];
        float4 p4 = p4p[i];
        float4 s4 = h4p[i];  // hs1
        dv[4 * i + 0] = d4.x; dv[4 * i + 1] = d4.y; dv[4 * i + 2] = d4.z; dv[4 * i + 3] = d4.w;
        h[4 * i + 0] = fmaxf(d4.x * (p4.x + s4.x) + b1s[4 * i + 0], 0.f);
        h[4 * i + 1] = fmaxf(d4.y * (p4.y + s4.y) + b1s[4 * i + 1], 0.f);
        h[4 * i + 2] = fmaxf(d4.z * (p4.z + s4.z) + b1s[4 * i + 2], 0.f);
        h[4 * i + 3] = fmaxf(d4.w * (p4.w + s4.w) + b1s[4 * i + 3], 0.f);
    }
    float acc[CH];
#pragma unroll
    for (int j = 0; j < CH; j++) acc[j] = 0.f;
#pragma unroll
    for (int k = 0; k < CH; k++) {
        float hk = h[k];
#pragma unroll
        for (int j = 0; j < CH; j++) acc[j] = fmaf(hk, W2s[k * CH + j], acc[j]);
    }
#pragma unroll
    for (int i = 0; i < 4; i++) {
        h4p[i] = make_float4(dv[4 * i + 0] * acc[4 * i + 0],
                             dv[4 * i + 1] * acc[4 * i + 1],
                             dv[4 * i + 2] * acc[4 * i + 2],
                             dv[4 * i + 3] * acc[4 * i + 3]);  // hs2
    }
}

// ---------- out = dinv*(partial + hs2) + b2 ----------
__global__ void __launch_bounds__(256) k_out(
        const float* __restrict__ b2, float* __restrict__ out) {
    int n = blockIdx.x * blockDim.x + threadIdx.x;
    if (n >= N_NODES) return;
    float4* o4 = reinterpret_cast<float4*>(out);
    const float4* d4p = reinterpret_cast<const float4*>(&g_dinv[n * CH]);
    const float4* p4p = reinterpret_cast<const float4*>(&g_partial[n * CH]);
    const float4* s4p = reinterpret_cast<const float4*>(&g_h[n * CH]);
#pragma unroll
    for (int i = 0; i < 4; i++) {
        float4 d4 = d4p[i];
        float4 p4 = p4p[i];
        float4 s4 = s4p[i];
        float4 o;
        o.x = d4.x * (p4.x + s4.x) + __ldg(b2 + 4 * i + 0);
        o.y = d4.y * (p4.y + s4.y) + __ldg(b2 + 4 * i + 1);
        o.z = d4.z * (p4.z + s4.z) + __ldg(b2 + 4 * i + 2);
        o.w = d4.w * (p4.w + s4.w) + __ldg(b2 + 4 * i + 3);
        o4[n * 4 + i] = o;
    }
}

extern "C" void kernel_launch(void* const* d_in, const int* in_sizes, int n_in,
                              void* d_out, int out_size) {
    const float* x  = (const float*)d_in[0];
    const int*   ei = (const int*)d_in[1];
    const float* ea = (const float*)d_in[2];
    const float* We = (const float*)d_in[3];
    const float* be = (const float*)d_in[4];
    const float* W1 = (const float*)d_in[5];
    const float* b1 = (const float*)d_in[6];
    const float* W2 = (const float*)d_in[7];
    const float* b2 = (const float*)d_in[8];
    const int* srcp = ei;
    const int* dstp = ei + N_EDGES;
    float* out = (float*)d_out;

    const int nb_n  = (N_NODES + 255) / 256;
    const int nb_e  = (N_EDGES + 255) / 256;
    const int nb_nc = (N_NODES * CH + 127) / 128;
    const int nb_s  = (N_NODES + 63) / 64;

    k_zero_cnt      <<<nb_n, 256>>>();
    k_ew_hist       <<<nb_e, 256>>>(ea, We, be, dstp);  // ew (bit-contract) + histogram
    k_scan_block    <<<NB_SCAN, 256>>>();
    k_scan_tot      <<<1, 512>>>();
    k_scan_add      <<<nb_n, 256>>>();
    k_fill          <<<nb_e, 256>>>(dstp);
    k_sort          <<<nb_s, 64>>>();
    k_xw            <<<nb_n, 256>>>(x, W1);
    k_deg_dinv_hs1  <<<nb_nc, 128>>>();                 // bit-contract sequential deg
    k_gather        <<<nb_nc, 128>>>(srcp);             // layer-1 aggregation (gather)
    k_layer1_finish <<<nb_n, 256>>>(b1, W2);
    k_gather        <<<nb_nc, 128>>>(srcp);             // layer-2 aggregation (gather)
    k_out           <<<nb_n, 256>>>(b2, out);
}

// round 16
// speedup vs baseline: 1.1192x; 1.0123x over previous
#include <cuda_runtime.h>

#define N_NODES 100000
#define N_EDGES 3200000
#define CH      16
#define INC     128
#define NB_SCAN 391   // ceil(N_NODES/256)

// Scratch (static __device__ arrays — allocation-free per harness rules)
static __device__ __align__(16) float g_ew[(size_t)N_EDGES * CH];   // [E,16]
static __device__ __align__(16) float g_dinv[N_NODES * CH];
static __device__ __align__(16) float g_h[N_NODES * CH];            // h1lin->hs1->hs2
static __device__ __align__(16) float g_partial[N_NODES * CH];
static __device__ int g_cnt[N_NODES];
static __device__ int g_rowptr[N_NODES + 1];
static __device__ int g_bsum[512];
static __device__ int g_boff[512];
static __device__ int g_cursor[N_NODES];
static __device__ int g_elist[N_EDGES];

// ---------- CSR build ----------
__global__ void k_zero_cnt(void) {
    int i = blockIdx.x * blockDim.x + threadIdx.x;
    if (i < N_NODES) g_cnt[i] = 0;
}

// ---------- ew = edge_attr @ We + be  (+ fused dst histogram) ----------
// BIT-CONTRACT (matches reference): 4 FUSED lane accumulators (lane = k mod 4)
// over ascending k-groups, pairwise combine (l0+l1)+(l2+l3), bias last.
__global__ void __launch_bounds__(256) k_ew_hist(
        const float* __restrict__ ea, const float* __restrict__ We,
        const float* __restrict__ be, const int* __restrict__ dstp) {
    __shared__ __align__(16) float Wt[CH * CH];   // Wt[j*16+k] = We[k*16+j]
    __shared__ float bs[CH];
    if (threadIdx.x < CH * CH) {
        int k = threadIdx.x / CH, j = threadIdx.x % CH;
        Wt[j * CH + k] = We[threadIdx.x];
    }
    if (threadIdx.x < CH) bs[threadIdx.x] = be[threadIdx.x];
    __syncthreads();
    int e = blockIdx.x * blockDim.x + threadIdx.x;
    if (e >= N_EDGES) return;
    const float4* ear = reinterpret_cast<const float4*>(ea) + (size_t)e * 4;
    float4 a0 = __ldcs(ear + 0), a1 = __ldcs(ear + 1);
    float4 a2 = __ldcs(ear + 2), a3 = __ldcs(ear + 3);
    float av[CH] = {a0.x, a0.y, a0.z, a0.w, a1.x, a1.y, a1.z, a1.w,
                    a2.x, a2.y, a2.z, a2.w, a3.x, a3.y, a3.z, a3.w};
    float w[CH];
#pragma unroll
    for (int j = 0; j < CH; j++) {
        const float4* wr = reinterpret_cast<const float4*>(&Wt[j * CH]);
        float4 q0 = wr[0], q1 = wr[1], q2 = wr[2], q3 = wr[3];
        float acc0 = 0.f, acc1 = 0.f, acc2 = 0.f, acc3 = 0.f;
        acc0 = fmaf(av[0],  q0.x, acc0);  acc1 = fmaf(av[1],  q0.y, acc1);
        acc2 = fmaf(av[2],  q0.z, acc2);  acc3 = fmaf(av[3],  q0.w, acc3);
        acc0 = fmaf(av[4],  q1.x, acc0);  acc1 = fmaf(av[5],  q1.y, acc1);
        acc2 = fmaf(av[6],  q1.z, acc2);  acc3 = fmaf(av[7],  q1.w, acc3);
        acc0 = fmaf(av[8],  q2.x, acc0);  acc1 = fmaf(av[9],  q2.y, acc1);
        acc2 = fmaf(av[10], q2.z, acc2);  acc3 = fmaf(av[11], q2.w, acc3);
        acc0 = fmaf(av[12], q3.x, acc0);  acc1 = fmaf(av[13], q3.y, acc1);
        acc2 = fmaf(av[14], q3.z, acc2);  acc3 = fmaf(av[15], q3.w, acc3);
        float s01 = __fadd_rn(acc0, acc1);
        float s23 = __fadd_rn(acc2, acc3);
        w[j] = __fadd_rn(__fadd_rn(s01, s23), bs[j]);
    }
    float4* ewp = reinterpret_cast<float4*>(&g_ew[(size_t)e * CH]);
    __stcs(ewp + 0, make_float4(w[0],  w[1],  w[2],  w[3]));
    __stcs(ewp + 1, make_float4(w[4],  w[5],  w[6],  w[7]));
    __stcs(ewp + 2, make_float4(w[8],  w[9],  w[10], w[11]));
    __stcs(ewp + 3, make_float4(w[12], w[13], w[14], w[15]));
    atomicAdd(&g_cnt[__ldg(dstp + e)], 1);   // fused histogram
}

__global__ void k_scan_block(void) {
    __shared__ int s[256];
    int i = blockIdx.x * 256 + threadIdx.x;
    int v = (i < N_NODES) ? g_cnt[i] : 0;
    s[threadIdx.x] = v;
    __syncthreads();
#pragma unroll
    for (int off = 1; off < 256; off <<= 1) {
        int t = (threadIdx.x >= off) ? s[threadIdx.x - off] : 0;
        __syncthreads();
        s[threadIdx.x] += t;
        __syncthreads();
    }
    if (i < N_NODES) g_rowptr[i] = s[threadIdx.x] - v;  // exclusive within block
    if (threadIdx.x == 255) g_bsum[blockIdx.x] = s[255];
}

__global__ void k_scan_tot(void) {
    __shared__ int s[512];
    int tid = threadIdx.x;
    int v = (tid < NB_SCAN) ? g_bsum[tid] : 0;
    s[tid] = v;
    __syncthreads();
#pragma unroll
    for (int off = 1; off < 512; off <<= 1) {
        int t = (tid >= off) ? s[tid - off] : 0;
        __syncthreads();
        s[tid] += t;
        __syncthreads();
    }
    g_boff[tid] = s[tid] - v;  // exclusive
}

__global__ void k_scan_add(void) {
    int i = blockIdx.x * blockDim.x + threadIdx.x;
    if (i < N_NODES) {
        g_rowptr[i] += g_boff[i >> 8];
        g_cursor[i] = 0;
    }
    if (i == 0) g_rowptr[N_NODES] = N_EDGES;
}

__global__ void k_fill(const int* __restrict__ dstp) {
    int e = blockIdx.x * blockDim.x + threadIdx.x;
    if (e >= N_EDGES) return;
    int d = dstp[e];
    int pos = g_rowptr[d] + atomicAdd(&g_cursor[d], 1);
    g_elist[pos] = e;
}

// Per-node ascending sort of edge ids — staged in shared memory.
__global__ void __launch_bounds__(64) k_sort(void) {
    __shared__ int buf[64][97];
    int n = blockIdx.x * 64 + threadIdx.x;
    if (n >= N_NODES) return;
    int lo = g_rowptr[n], hi = g_rowptr[n + 1];
    int L = hi - lo;
    if (L <= 96) {
        int* b = buf[threadIdx.x];
        for (int i = 0; i < L; i++) b[i] = g_elist[lo + i];
        for (int i = 1; i < L; i++) {
            int v = b[i];
            int j = i - 1;
            while (j >= 0 && b[j] > v) { b[j + 1] = b[j]; j--; }
            b[j + 1] = v;
        }
        for (int i = 0; i < L; i++) g_elist[lo + i] = b[i];
    } else {
        for (int i = lo + 1; i < hi; i++) {
            int v = g_elist[i];
            int j = i - 1;
            while (j >= lo && g_elist[j] > v) { g_elist[j + 1] = g_elist[j]; j--; }
            g_elist[j + 1] = v;
        }
    }
}

// ---------- h1lin = x @ W1 (fp32; non-amplified) ----------
__global__ void __launch_bounds__(256) k_xw(
        const float* __restrict__ x, const float* __restrict__ W1) {
    __shared__ float W1s[INC * CH];
    for (int i = threadIdx.x; i < INC * CH; i += blockDim.x) W1s[i] = W1[i];
    __syncthreads();
    int n = blockIdx.x * blockDim.x + threadIdx.x;
    if (n >= N_NODES) return;
    float acc[CH];
#pragma unroll
    for (int j = 0; j < CH; j++) acc[j] = 0.f;
    const float4* xr = reinterpret_cast<const float4*>(x) + (size_t)n * (INC / 4);
#pragma unroll 4
    for (int k4 = 0; k4 < INC / 4; k4++) {
        float4 xv = __ldg(xr + k4);
        const float* w0 = &W1s[(k4 * 4 + 0) * CH];
        const float* w1 = &W1s[(k4 * 4 + 1) * CH];
        const float* w2 = &W1s[(k4 * 4 + 2) * CH];
        const float* w3 = &W1s[(k4 * 4 + 3) * CH];
#pragma unroll
        for (int j = 0; j < CH; j++) {
            acc[j] = fmaf(xv.x, w0[j], acc[j]);
            acc[j] = fmaf(xv.y, w1[j], acc[j]);
            acc[j] = fmaf(xv.z, w2[j], acc[j]);
            acc[j] = fmaf(xv.w, w3[j], acc[j]);
        }
    }
    float4* hp = reinterpret_cast<float4*>(&g_h[n * CH]);
#pragma unroll
    for (int i = 0; i < 4; i++)
        hp[i] = make_float4(acc[4 * i], acc[4 * i + 1], acc[4 * i + 2], acc[4 * i + 3]);
}

// ---------- deg: BIT-CONTRACT sequential ascending-e fp32 sum, +1.0 last ----------
// R16: loads batched 2-ahead; adds remain strictly in ascending order (bit-exact).
__global__ void __launch_bounds__(256) k_deg_dinv_hs1(void) {
    int t = blockIdx.x * blockDim.x + threadIdx.x;
    int n = t >> 4;
    int c = t & 15;
    if (n >= N_NODES) return;
    int lo = g_rowptr[n], hi = g_rowptr[n + 1];
    float acc = 0.f;
    int i = lo;
    for (; i + 2 <= hi; i += 2) {
        int e0 = __ldg(&g_elist[i]);
        int e1 = __ldg(&g_elist[i + 1]);
        float w0 = __ldg(&g_ew[(size_t)e0 * CH + c]);
        float w1 = __ldg(&g_ew[(size_t)e1 * CH + c]);
        acc = __fadd_rn(acc, w0);        // in-order adds
        acc = __fadd_rn(acc, w1);
    }
    if (i < hi) {
        int e0 = __ldg(&g_elist[i]);
        acc = __fadd_rn(acc, __ldg(&g_ew[(size_t)e0 * CH + c]));
    }
    float deg = __fadd_rn(acc, 1.0f);
    float dinv = 0.f;
    if (deg > 0.f) {
        double dd = (double)fabsf(deg) + 1e-12;
        dinv = (float)(1.0 / sqrt(dd));
    }
    int idx = n * CH + c;
    g_dinv[idx] = dinv;
    g_h[idx] = dinv * g_h[idx];  // hs1
}

// ---------- layer aggregation as CSR GATHER (no atomics), ILP=2 ----------
// partial[n,c] = Σ_{e in CSR[n]} ew[e,c] * hs[src[e],c]
// (layer sums are NOT bit-contracted: two accumulators, combined at end)
__global__ void __launch_bounds__(256) k_gather(const int* __restrict__ srcp) {
    int t = blockIdx.x * blockDim.x + threadIdx.x;
    int n = t >> 4;
    int c = t & 15;
    if (n >= N_NODES) return;
    int lo = g_rowptr[n], hi = g_rowptr[n + 1];
    float accA = 0.f, accB = 0.f;
    int i = lo;
    for (; i + 2 <= hi; i += 2) {
        int e0 = __ldg(&g_elist[i]);
        int e1 = __ldg(&g_elist[i + 1]);
        int s0 = __ldg(srcp + e0);
        int s1 = __ldg(srcp + e1);
        float w0 = __ldg(&g_ew[(size_t)e0 * CH + c]);
        float w1 = __ldg(&g_ew[(size_t)e1 * CH + c]);
        float h0 = __ldg(&g_h[s0 * CH + c]);
        float h1 = __ldg(&g_h[s1 * CH + c]);
        accA = fmaf(w0, h0, accA);
        accB = fmaf(w1, h1, accB);
    }
    if (i < hi) {
        int e0 = __ldg(&g_elist[i]);
        int s0 = __ldg(srcp + e0);
        accA = fmaf(__ldg(&g_ew[(size_t)e0 * CH + c]), __ldg(&g_h[s0 * CH + c]), accA);
    }
    g_partial[n * CH + c] = accA + accB;   // plain store — no atomics
}

// ---------- layer-1 finish: h = relu(dinv*(partial+hs1)+b1); hs2 = dinv*(h@W2) ----------
__global__ void __launch_bounds__(256) k_layer1_finish(
        const float* __restrict__ b1, const float* __restrict__ W2) {
    __shared__ float W2s[CH * CH];
    __shared__ float b1s[CH];
    if (threadIdx.x < CH * CH) W2s[threadIdx.x] = W2[threadIdx.x];
    if (threadIdx.x < CH) b1s[threadIdx.x] = b1[threadIdx.x];
    __syncthreads();
    int n = blockIdx.x * blockDim.x + threadIdx.x;
    if (n >= N_NODES) return;
    float h[CH], dv[CH];
    const float4* d4p = reinterpret_cast<const float4*>(&g_dinv[n * CH]);
    const float4* p4p = reinterpret_cast<const float4*>(&g_partial[n * CH]);
    float4* h4p = reinterpret_cast<float4*>(&g_h[n * CH]);
#pragma unroll
    for (int i = 0; i < 4; i++) {
        float4 d4 = d4p[i];
        float4 p4 = p4p[i];
        float4 s4 = h4p[i];  // hs1
        dv[4 * i + 0] = d4.x; dv[4 * i + 1] = d4.y; dv[4 * i + 2] = d4.z; dv[4 * i + 3] = d4.w;
        h[4 * i + 0] = fmaxf(d4.x * (p4.x + s4.x) + b1s[4 * i + 0], 0.f);
        h[4 * i + 1] = fmaxf(d4.y * (p4.y + s4.y) + b1s[4 * i + 1], 0.f);
        h[4 * i + 2] = fmaxf(d4.z * (p4.z + s4.z) + b1s[4 * i + 2], 0.f);
        h[4 * i + 3] = fmaxf(d4.w * (p4.w + s4.w) + b1s[4 * i + 3], 0.f);
    }
    float acc[CH];
#pragma unroll
    for (int j = 0; j < CH; j++) acc[j] = 0.f;
#pragma unroll
    for (int k = 0; k < CH; k++) {
        float hk = h[k];
#pragma unroll
        for (int j = 0; j < CH; j++) acc[j] = fmaf(hk, W2s[k * CH + j], acc[j]);
    }
#pragma unroll
    for (int i = 0; i < 4; i++) {
        h4p[i] = make_float4(dv[4 * i + 0] * acc[4 * i + 0],
                             dv[4 * i + 1] * acc[4 * i + 1],
                             dv[4 * i + 2] * acc[4 * i + 2],
                             dv[4 * i + 3] * acc[4 * i + 3]);  // hs2
    }
}

// ---------- out = dinv*(partial + hs2) + b2 ----------
__global__ void __launch_bounds__(256) k_out(
        const float* __restrict__ b2, float* __restrict__ out) {
    int n = blockIdx.x * blockDim.x + threadIdx.x;
    if (n >= N_NODES) return;
    float4* o4 = reinterpret_cast<float4*>(out);
    const float4* d4p = reinterpret_cast<const float4*>(&g_dinv[n * CH]);
    const float4* p4p = reinterpret_cast<const float4*>(&g_partial[n * CH]);
    const float4* s4p = reinterpret_cast<const float4*>(&g_h[n * CH]);
#pragma unroll
    for (int i = 0; i < 4; i++) {
        float4 d4 = d4p[i];
        float4 p4 = p4p[i];
        float4 s4 = s4p[i];
        float4 o;
        o.x = d4.x * (p4.x + s4.x) + __ldg(b2 + 4 * i + 0);
        o.y = d4.y * (p4.y + s4.y) + __ldg(b2 + 4 * i + 1);
        o.z = d4.z * (p4.z + s4.z) + __ldg(b2 + 4 * i + 2);
        o.w = d4.w * (p4.w + s4.w) + __ldg(b2 + 4 * i + 3);
        o4[n * 4 + i] = o;
    }
}

extern "C" void kernel_launch(void* const* d_in, const int* in_sizes, int n_in,
                              void* d_out, int out_size) {
    const float* x  = (const float*)d_in[0];
    const int*   ei = (const int*)d_in[1];
    const float* ea = (const float*)d_in[2];
    const float* We = (const float*)d_in[3];
    const float* be = (const float*)d_in[4];
    const float* W1 = (const float*)d_in[5];
    const float* b1 = (const float*)d_in[6];
    const float* W2 = (const float*)d_in[7];
    const float* b2 = (const float*)d_in[8];
    const int* srcp = ei;
    const int* dstp = ei + N_EDGES;
    float* out = (float*)d_out;

    const int nb_n  = (N_NODES + 255) / 256;
    const int nb_e  = (N_EDGES + 255) / 256;
    const int nb_nc = (N_NODES * CH + 255) / 256;
    const int nb_s  = (N_NODES + 63) / 64;

    k_zero_cnt      <<<nb_n, 256>>>();
    k_ew_hist       <<<nb_e, 256>>>(ea, We, be, dstp);  // ew (bit-contract) + histogram
    k_scan_block    <<<NB_SCAN, 256>>>();
    k_scan_tot      <<<1, 512>>>();
    k_scan_add      <<<nb_n, 256>>>();
    k_fill          <<<nb_e, 256>>>(dstp);
    k_sort          <<<nb_s, 64>>>();
    k_xw            <<<nb_n, 256>>>(x, W1);
    k_deg_dinv_hs1  <<<nb_nc, 256>>>();                 // bit-contract deg, batched loads
    k_gather        <<<nb_nc, 256>>>(srcp);             // layer-1 aggregation (ILP=2)
    k_layer1_finish <<<nb_n, 256>>>(b1, W2);
    k_gather        <<<nb_nc, 256>>>(srcp);             // layer-2 aggregation (ILP=2)
    k_out           <<<nb_n, 256>>>(b2, out);
}